// round 1
// baseline (speedup 1.0000x reference)
#include <cuda_runtime.h>
#include <cstdint>

#define NSPB 32                    // sites per block
#define THREADS (NSPB * 9)         // 288
#define SITE_STRIDE 164            // floats per site in smem (144 data + 18 identity + 2 pad; 656B, 16B-aligned)

__device__ __forceinline__ unsigned long long pack2(float lo, float hi) {
    unsigned long long r;
    asm("mov.b64 %0, {%1,%2};" : "=l"(r) : "f"(lo), "f"(hi));
    return r;
}
__device__ __forceinline__ void unpack2(unsigned long long v, float& lo, float& hi) {
    asm("mov.b64 {%0,%1}, %2;" : "=f"(lo), "=f"(hi) : "l"(v));
}
__device__ __forceinline__ unsigned long long ffma2(unsigned long long a, unsigned long long b,
                                                    unsigned long long c) {
    unsigned long long d;
    asm("fma.rn.f32x2 %0, %1, %2, %3;" : "=l"(d) : "l"(a), "l"(b), "l"(c));
    return d;
}
__device__ __forceinline__ unsigned long long fmul2(unsigned long long a, unsigned long long b) {
    unsigned long long d;
    asm("mul.rn.f32x2 %0, %1, %2;" : "=l"(d) : "l"(a), "l"(b));
    return d;
}

__global__ __launch_bounds__(THREADS)
void lbilin_kernel(const float* __restrict__ u,
                   const float* __restrict__ w1,
                   const float* __restrict__ w2,
                   const float* __restrict__ weight,
                   float* __restrict__ out_u,
                   float* __restrict__ out_w)
{
    __shared__ float s_w1[NSPB * SITE_STRIDE];
    __shared__ float s_w2[NSPB * SITE_STRIDE];
    __shared__ unsigned long long s_wd[648];   // weight duplicated as (w,w) pairs, layout [(v*9+w)*8+u]

    const int tid = threadIdx.x;
    const long long site0 = (long long)blockIdx.x * NSPB;

    // ---- u passthrough: 32 sites * 72 floats = 576 float4 per block ----
    {
        const float4* src = (const float4*)(u + site0 * 72);
        float4*       dst = (float4*)(out_u + site0 * 72);
        #pragma unroll
        for (int idx = tid; idx < NSPB * 18; idx += THREADS)
            dst[idx] = src[idx];
    }

    // ---- weight: duplicate each scalar into a float2 for FFMA2 broadcast ----
    for (int d = tid; d < 648; d += THREADS) {
        int uo = d & 7;
        int vw = d >> 3;
        float wv = weight[uo * 81 + vw];
        s_wd[d] = pack2(wv, wv);
    }

    // ---- stage w1, w2 tiles (144 contiguous floats/site) ----
    {
        const float4* g1 = (const float4*)(w1 + site0 * 144);
        const float4* g2 = (const float4*)(w2 + site0 * 144);
        for (int idx = tid; idx < NSPB * 36; idx += THREADS) {
            int s = idx / 36;
            int q = idx - s * 36;
            ((float4*)(s_w1 + s * SITE_STRIDE))[q] = g1[idx];
            ((float4*)(s_w2 + s * SITE_STRIDE))[q] = g2[idx];
        }
    }
    // identity channel (index 8) at float offset 144 within each site
    {
        int s = tid / 9, e = tid - (tid / 9) * 9;
        int ii = e / 3, jj = e - ii * 3;
        float re = (ii == jj) ? 1.0f : 0.0f;
        float* p1 = s_w1 + s * SITE_STRIDE + 144 + e * 2;
        float* p2 = s_w2 + s * SITE_STRIDE + 144 + e * 2;
        p1[0] = re; p1[1] = 0.0f;
        p2[0] = re; p2[1] = 0.0f;
    }
    __syncthreads();

    const int sl = tid / 9;
    const int ik = tid - sl * 9;
    const int i  = ik / 3;
    const int k  = ik - i * 3;
    const long long site = site0 + sl;

    // b[w][j] = w2e[site, w, j, k]  (27 packed complex values, fixed k)
    unsigned long long b[27];
    {
        const unsigned long long* w2p = (const unsigned long long*)(s_w2 + sl * SITE_STRIDE);
        #pragma unroll
        for (int w = 0; w < 9; w++)
            #pragma unroll
            for (int j = 0; j < 3; j++)
                b[w * 3 + j] = w2p[w * 9 + j * 3 + k];
    }

    unsigned long long acc[8];
    #pragma unroll
    for (int uo = 0; uo < 8; uo++) acc[uo] = 0ULL;

    const unsigned long long* w1p = (const unsigned long long*)(s_w1 + sl * SITE_STRIDE);
    const unsigned long long NEGPOS = pack2(-1.0f, 1.0f);

    #pragma unroll 3
    for (int v = 0; v < 9; v++) {
        float a0R, a0I, a1R, a1I, a2R, a2I;
        unpack2(w1p[v * 9 + i * 3 + 0], a0R, a0I);
        unpack2(w1p[v * 9 + i * 3 + 1], a1R, a1I);
        unpack2(w1p[v * 9 + i * 3 + 2], a2R, a2I);
        unsigned long long aR0 = pack2(a0R, a0R), aR1 = pack2(a1R, a1R), aR2 = pack2(a2R, a2R);
        unsigned long long aI0 = pack2(a0I, a0I), aI1 = pack2(a1I, a1I), aI2 = pack2(a2I, a2I);

        #pragma unroll
        for (int w = 0; w < 9; w++) {
            // s = (Sum aR*bR, Sum aR*bI) ; t = (Sum aI*bR, Sum aI*bI)
            unsigned long long s2 = fmul2(aR0, b[w * 3 + 0]);
            s2 = ffma2(aR1, b[w * 3 + 1], s2);
            s2 = ffma2(aR2, b[w * 3 + 2], s2);
            unsigned long long t2 = fmul2(aI0, b[w * 3 + 0]);
            t2 = ffma2(aI1, b[w * 3 + 1], t2);
            t2 = ffma2(aI2, b[w * 3 + 2], t2);
            // cval = (s.lo - t.hi, s.hi + t.lo) = swap(t) * (-1,+1) + s
            float tl, th;
            unpack2(t2, tl, th);
            unsigned long long tsw = pack2(th, tl);
            unsigned long long cpk = ffma2(tsw, NEGPOS, s2);

            const unsigned long long* wd = s_wd + (v * 9 + w) * 8;
            #pragma unroll
            for (int uo = 0; uo < 8; uo++)
                acc[uo] = ffma2(wd[uo], cpk, acc[uo]);
        }
    }

    // store w[u, i, k, {re,im}] : float2 at offset (u*9 + ik)*2
    float2* op = (float2*)(out_w + site * 144 + ik * 2);
    #pragma unroll
    for (int uo = 0; uo < 8; uo++) {
        float lo, hi;
        unpack2(acc[uo], lo, hi);
        op[uo * 9] = make_float2(lo, hi);
    }
}

extern "C" void kernel_launch(void* const* d_in, const int* in_sizes, int n_in,
                              void* d_out, int out_size) {
    const float* u  = (const float*)d_in[0];
    const float* w1 = (const float*)d_in[1];
    const float* w2 = (const float*)d_in[2];
    const float* wt = (const float*)d_in[3];

    int nsites = in_sizes[1] / 144;          // 65536
    float* out   = (float*)d_out;
    float* out_u = out;                       // u passthrough first
    float* out_w = out + (long long)nsites * 72;  // then mixed output

    int blocks = nsites / NSPB;               // 2048
    lbilin_kernel<<<blocks, THREADS>>>(u, w1, w2, wt, out_u, out_w);
}

// round 2
// speedup vs baseline: 1.5682x; 1.5682x over previous
#include <cuda_runtime.h>
#include <cstdint>

#define NSPB 32                    // sites per block
#define THREADS (NSPB * 9)         // 288
#define S1_STRIDE 148              // floats per site in s_w1 (144 + 4 pad; 592B, 16B aligned)
#define S2_STRIDE 164              // floats per site in s_w2 (144 + 18 identity + 2 pad)

__device__ __forceinline__ unsigned long long pack2(float lo, float hi) {
    unsigned long long r;
    asm("mov.b64 %0, {%1,%2};" : "=l"(r) : "f"(lo), "f"(hi));
    return r;
}
__device__ __forceinline__ void unpack2(unsigned long long v, float& lo, float& hi) {
    asm("mov.b64 {%0,%1}, %2;" : "=f"(lo), "=f"(hi) : "l"(v));
}
__device__ __forceinline__ unsigned long long ffma2(unsigned long long a, unsigned long long b,
                                                    unsigned long long c) {
    unsigned long long d;
    asm("fma.rn.f32x2 %0, %1, %2, %3;" : "=l"(d) : "l"(a), "l"(b), "l"(c));
    return d;
}
__device__ __forceinline__ unsigned long long fmul2(unsigned long long a, unsigned long long b) {
    unsigned long long d;
    asm("mul.rn.f32x2 %0, %1, %2;" : "=l"(d) : "l"(a), "l"(b));
    return d;
}

__global__ __launch_bounds__(THREADS, 2)
void lbilin_kernel(const float* __restrict__ u,
                   const float* __restrict__ w1,
                   const float* __restrict__ w2,
                   const float* __restrict__ weight,
                   float* __restrict__ out_u,
                   float* __restrict__ out_w)
{
    __shared__ float s_w1[NSPB * S1_STRIDE];
    __shared__ float s_w2[NSPB * S2_STRIDE];
    __shared__ ulonglong2 s_wd[324];   // weight duplicated as (w,w) pairs: [(v*9+w)*4 + h]

    const int tid = threadIdx.x;
    const long long site0 = (long long)blockIdx.x * NSPB;

    // ---- u passthrough: 32 sites * 72 floats = 576 float4 per block ----
    {
        const float4* src = (const float4*)(u + site0 * 72);
        float4*       dst = (float4*)(out_u + site0 * 72);
        #pragma unroll
        for (int idx = tid; idx < NSPB * 18; idx += THREADS)
            dst[idx] = src[idx];
    }

    // ---- weight: duplicate each scalar into a u64 pair, 16B-grouped ----
    {
        unsigned long long* wd64 = (unsigned long long*)s_wd;
        for (int d = tid; d < 648; d += THREADS) {
            int uo = d & 7;
            int vw = d >> 3;
            float wv = weight[uo * 81 + vw];
            wd64[d] = pack2(wv, wv);
        }
    }

    // ---- stage w1, w2 tiles (144 contiguous floats/site) ----
    {
        const float4* g1 = (const float4*)(w1 + site0 * 144);
        const float4* g2 = (const float4*)(w2 + site0 * 144);
        for (int idx = tid; idx < NSPB * 36; idx += THREADS) {
            int s = idx / 36;
            int q = idx - s * 36;
            ((float4*)(s_w1 + s * S1_STRIDE))[q] = g1[idx];
            ((float4*)(s_w2 + s * S2_STRIDE))[q] = g2[idx];
        }
    }
    // identity channel (w=8) for w2 at float offset 144 within each site
    {
        int s = tid / 9, e = tid - (tid / 9) * 9;
        int ii = e / 3, jj = e - ii * 3;
        float* p2 = s_w2 + s * S2_STRIDE + 144 + e * 2;
        p2[0] = (ii == jj) ? 1.0f : 0.0f;
        p2[1] = 0.0f;
    }
    __syncthreads();

    const int sl = tid / 9;
    const int ik = tid - sl * 9;
    const int i  = ik / 3;
    const int k  = ik - i * 3;
    const long long site = site0 + sl;

    const unsigned long long* w1p = (const unsigned long long*)(s_w1 + sl * S1_STRIDE);
    const unsigned long long* w2p = (const unsigned long long*)(s_w2 + sl * S2_STRIDE);

    // b[w][j] = w2e[site, w, j, k]  for w<8 (24 packed complex values, fixed k)
    unsigned long long b[24];
    #pragma unroll
    for (int w = 0; w < 8; w++)
        #pragma unroll
        for (int j = 0; j < 3; j++)
            b[w * 3 + j] = w2p[w * 9 + j * 3 + k];

    unsigned long long acc[8];
    #pragma unroll
    for (int uo = 0; uo < 8; uo++) acc[uo] = 0ULL;

    const unsigned long long NEGPOS = pack2(-1.0f, 1.0f);

    #pragma unroll 2
    for (int v = 0; v < 8; v++) {
        float a0R, a0I, a1R, a1I, a2R, a2I;
        unpack2(w1p[v * 9 + i * 3 + 0], a0R, a0I);
        unpack2(w1p[v * 9 + i * 3 + 1], a1R, a1I);
        unpack2(w1p[v * 9 + i * 3 + 2], a2R, a2I);
        unsigned long long aR0 = pack2(a0R, a0R), aR1 = pack2(a1R, a1R), aR2 = pack2(a2R, a2R);
        unsigned long long aI0 = pack2(a0I, a0I), aI1 = pack2(a1I, a1I), aI2 = pack2(a2I, a2I);

        #pragma unroll
        for (int w = 0; w < 8; w++) {
            // s = (Sum aR*bR, Sum aR*bI) ; t = (Sum aI*bR, Sum aI*bI)
            unsigned long long s2 = fmul2(aR0, b[w * 3 + 0]);
            s2 = ffma2(aR1, b[w * 3 + 1], s2);
            s2 = ffma2(aR2, b[w * 3 + 2], s2);
            unsigned long long t2 = fmul2(aI0, b[w * 3 + 0]);
            t2 = ffma2(aI1, b[w * 3 + 1], t2);
            t2 = ffma2(aI2, b[w * 3 + 2], t2);
            // cval = (s.lo - t.hi, s.hi + t.lo) = swap(t) * (-1,+1) + s
            float tl, th;
            unpack2(t2, tl, th);
            unsigned long long cpk = ffma2(pack2(th, tl), NEGPOS, s2);

            const ulonglong2* wd = s_wd + (v * 9 + w) * 4;
            #pragma unroll
            for (int h = 0; h < 4; h++) {
                ulonglong2 wp = wd[h];
                acc[2 * h + 0] = ffma2(wp.x, cpk, acc[2 * h + 0]);
                acc[2 * h + 1] = ffma2(wp.y, cpk, acc[2 * h + 1]);
            }
        }
        // w = 8: B is identity -> c[v,8] = A_v[i,k]
        {
            unsigned long long cpk = w1p[v * 9 + i * 3 + k];
            const ulonglong2* wd = s_wd + (v * 9 + 8) * 4;
            #pragma unroll
            for (int h = 0; h < 4; h++) {
                ulonglong2 wp = wd[h];
                acc[2 * h + 0] = ffma2(wp.x, cpk, acc[2 * h + 0]);
                acc[2 * h + 1] = ffma2(wp.y, cpk, acc[2 * h + 1]);
            }
        }
    }
    // v = 8: A is identity -> c[8,w] = B_w[i,k]  (includes w=8 via staged identity)
    #pragma unroll
    for (int w = 0; w < 9; w++) {
        unsigned long long cpk = w2p[w * 9 + i * 3 + k];
        const ulonglong2* wd = s_wd + (8 * 9 + w) * 4;
        #pragma unroll
        for (int h = 0; h < 4; h++) {
            ulonglong2 wp = wd[h];
            acc[2 * h + 0] = ffma2(wp.x, cpk, acc[2 * h + 0]);
            acc[2 * h + 1] = ffma2(wp.y, cpk, acc[2 * h + 1]);
        }
    }

    // store w[u, i, k, {re,im}] : float2 at offset (u*9 + ik)*2
    float2* op = (float2*)(out_w + site * 144 + ik * 2);
    #pragma unroll
    for (int uo = 0; uo < 8; uo++) {
        float lo, hi;
        unpack2(acc[uo], lo, hi);
        op[uo * 9] = make_float2(lo, hi);
    }
}

extern "C" void kernel_launch(void* const* d_in, const int* in_sizes, int n_in,
                              void* d_out, int out_size) {
    const float* u  = (const float*)d_in[0];
    const float* w1 = (const float*)d_in[1];
    const float* w2 = (const float*)d_in[2];
    const float* wt = (const float*)d_in[3];

    int nsites = in_sizes[1] / 144;          // 65536
    float* out   = (float*)d_out;
    float* out_u = out;                       // u passthrough first
    float* out_w = out + (long long)nsites * 72;  // then mixed output

    int blocks = nsites / NSPB;               // 2048
    lbilin_kernel<<<blocks, THREADS>>>(u, w1, w2, wt, out_u, out_w);
}

// round 3
// speedup vs baseline: 1.6516x; 1.0531x over previous
#include <cuda_runtime.h>
#include <cstdint>

#define NSPB 32                    // sites per block
#define THREADS (NSPB * 9)         // 288
#define S1_STRIDE 148              // floats per site in s_w1 (144 + 4 pad)
#define S2_STRIDE 164              // floats per site in s_w2 (144 + 18 identity + 2 pad)

__device__ __forceinline__ unsigned long long pack2(float lo, float hi) {
    unsigned long long r;
    asm("mov.b64 %0, {%1,%2};" : "=l"(r) : "f"(lo), "f"(hi));
    return r;
}
__device__ __forceinline__ void unpack2(unsigned long long v, float& lo, float& hi) {
    asm("mov.b64 {%0,%1}, %2;" : "=f"(lo), "=f"(hi) : "l"(v));
}
__device__ __forceinline__ unsigned long long ffma2(unsigned long long a, unsigned long long b,
                                                    unsigned long long c) {
    unsigned long long d;
    asm("fma.rn.f32x2 %0, %1, %2, %3;" : "=l"(d) : "l"(a), "l"(b), "l"(c));
    return d;
}
__device__ __forceinline__ unsigned long long fmul2(unsigned long long a, unsigned long long b) {
    unsigned long long d;
    asm("mul.rn.f32x2 %0, %1, %2;" : "=l"(d) : "l"(a), "l"(b));
    return d;
}

// One mixing step: acc{R,I}[0..3] += wt8 * (cR,cR)/(cI,cI), weights in natural float4 pairs
struct WPair { unsigned long long p01, p23, p45, p67; };

__device__ __forceinline__ void mix_step(const ulonglong2* __restrict__ wvw,
                                         unsigned long long cpk,
                                         unsigned long long* accR,
                                         unsigned long long* accI)
{
    float cR, cI;
    unpack2(cpk, cR, cI);
    unsigned long long cRR = pack2(cR, cR);
    unsigned long long cII = pack2(cI, cI);
    ulonglong2 lo = wvw[0];       // (w0,w1),(w2,w3)
    ulonglong2 hi = wvw[1];       // (w4,w5),(w6,w7)
    accR[0] = ffma2(lo.x, cRR, accR[0]);
    accI[0] = ffma2(lo.x, cII, accI[0]);
    accR[1] = ffma2(lo.y, cRR, accR[1]);
    accI[1] = ffma2(lo.y, cII, accI[1]);
    accR[2] = ffma2(hi.x, cRR, accR[2]);
    accI[2] = ffma2(hi.x, cII, accI[2]);
    accR[3] = ffma2(hi.y, cRR, accR[3]);
    accI[3] = ffma2(hi.y, cII, accI[3]);
}

__global__ __launch_bounds__(THREADS, 2)
void lbilin_kernel(const float* __restrict__ u,
                   const float* __restrict__ w1,
                   const float* __restrict__ w2,
                   const float* __restrict__ weight,
                   float* __restrict__ out_u,
                   float* __restrict__ out_w)
{
    __shared__ float s_w1[NSPB * S1_STRIDE];
    __shared__ float s_w2[NSPB * S2_STRIDE];
    __shared__ float s_wt[81 * 8];     // s_wt[vw*8 + u] = weight[u*81 + vw]  (natural scalars)

    const int tid = threadIdx.x;
    const long long site0 = (long long)blockIdx.x * NSPB;

    // ---- u passthrough: 32 sites * 72 floats = 576 float4 per block ----
    {
        const float4* src = (const float4*)(u + site0 * 72);
        float4*       dst = (float4*)(out_u + site0 * 72);
        #pragma unroll
        for (int idx = tid; idx < NSPB * 18; idx += THREADS)
            dst[idx] = src[idx];
    }

    // ---- weight transpose into smem: [vw][u], 32B per vw ----
    for (int d = tid; d < 648; d += THREADS) {
        int uo = d & 7;
        int vw = d >> 3;
        s_wt[d] = weight[uo * 81 + vw];
    }

    // ---- stage w1, w2 tiles (144 contiguous floats/site) ----
    {
        const float4* g1 = (const float4*)(w1 + site0 * 144);
        const float4* g2 = (const float4*)(w2 + site0 * 144);
        for (int idx = tid; idx < NSPB * 36; idx += THREADS) {
            int s = idx / 36;
            int q = idx - s * 36;
            ((float4*)(s_w1 + s * S1_STRIDE))[q] = g1[idx];
            ((float4*)(s_w2 + s * S2_STRIDE))[q] = g2[idx];
        }
    }
    // identity channel (w=8) for w2 at float offset 144 within each site
    {
        int s = tid / 9, e = tid - (tid / 9) * 9;
        int ii = e / 3, jj = e - ii * 3;
        float* p2 = s_w2 + s * S2_STRIDE + 144 + e * 2;
        p2[0] = (ii == jj) ? 1.0f : 0.0f;
        p2[1] = 0.0f;
    }
    __syncthreads();

    const int sl = tid / 9;
    const int ik = tid - sl * 9;
    const int i  = ik / 3;
    const int k  = ik - i * 3;
    const long long site = site0 + sl;

    const unsigned long long* w1p = (const unsigned long long*)(s_w1 + sl * S1_STRIDE);
    const unsigned long long* w2p = (const unsigned long long*)(s_w2 + sl * S2_STRIDE);
    const ulonglong2* wt2 = (const ulonglong2*)s_wt;   // 2 per vw

    // b[w][j] = w2e[site, w, j, k]  for w<8 (24 packed complex values, fixed k)
    unsigned long long b[24];
    #pragma unroll
    for (int w = 0; w < 8; w++)
        #pragma unroll
        for (int j = 0; j < 3; j++)
            b[w * 3 + j] = w2p[w * 9 + j * 3 + k];

    unsigned long long accR[4], accI[4];
    #pragma unroll
    for (int h = 0; h < 4; h++) { accR[h] = 0ULL; accI[h] = 0ULL; }

    const unsigned long long NEGPOS = pack2(-1.0f, 1.0f);

    #pragma unroll 2
    for (int v = 0; v < 8; v++) {
        float a0R, a0I, a1R, a1I, a2R, a2I;
        unpack2(w1p[v * 9 + i * 3 + 0], a0R, a0I);
        unpack2(w1p[v * 9 + i * 3 + 1], a1R, a1I);
        unpack2(w1p[v * 9 + i * 3 + 2], a2R, a2I);
        unsigned long long aR0 = pack2(a0R, a0R), aR1 = pack2(a1R, a1R), aR2 = pack2(a2R, a2R);
        unsigned long long aI0 = pack2(a0I, a0I), aI1 = pack2(a1I, a1I), aI2 = pack2(a2I, a2I);

        #pragma unroll
        for (int w = 0; w < 8; w++) {
            // s = (Sum aR*bR, Sum aR*bI) ; t = (Sum aI*bR, Sum aI*bI)
            unsigned long long s2 = fmul2(aR0, b[w * 3 + 0]);
            s2 = ffma2(aR1, b[w * 3 + 1], s2);
            s2 = ffma2(aR2, b[w * 3 + 2], s2);
            unsigned long long t2 = fmul2(aI0, b[w * 3 + 0]);
            t2 = ffma2(aI1, b[w * 3 + 1], t2);
            t2 = ffma2(aI2, b[w * 3 + 2], t2);
            float tl, th;
            unpack2(t2, tl, th);
            unsigned long long cpk = ffma2(pack2(th, tl), NEGPOS, s2);  // (cR, cI)
            mix_step(wt2 + (v * 9 + w) * 2, cpk, accR, accI);
        }
        // w = 8: B is identity -> c[v,8] = A_v[i,k]
        mix_step(wt2 + (v * 9 + 8) * 2, w1p[v * 9 + i * 3 + k], accR, accI);
    }
    // v = 8: A is identity -> c[8,w] = B_w[i,k]  (includes w=8 via staged identity)
    #pragma unroll
    for (int w = 0; w < 9; w++)
        mix_step(wt2 + (8 * 9 + w) * 2, w2p[w * 9 + i * 3 + k], accR, accI);

    // store w[u, i, k, {re,im}] : float2 at offset (u*9 + ik)*2
    float2* op = (float2*)(out_w + site * 144 + ik * 2);
    #pragma unroll
    for (int h = 0; h < 4; h++) {
        float r0, r1, i0, i1;
        unpack2(accR[h], r0, r1);
        unpack2(accI[h], i0, i1);
        op[(2 * h + 0) * 9] = make_float2(r0, i0);
        op[(2 * h + 1) * 9] = make_float2(r1, i1);
    }
}

extern "C" void kernel_launch(void* const* d_in, const int* in_sizes, int n_in,
                              void* d_out, int out_size) {
    const float* u  = (const float*)d_in[0];
    const float* w1 = (const float*)d_in[1];
    const float* w2 = (const float*)d_in[2];
    const float* wt = (const float*)d_in[3];

    int nsites = in_sizes[1] / 144;          // 65536
    float* out   = (float*)d_out;
    float* out_u = out;                       // u passthrough first
    float* out_w = out + (long long)nsites * 72;  // then mixed output

    int blocks = nsites / NSPB;               // 2048
    lbilin_kernel<<<blocks, THREADS>>>(u, w1, w2, wt, out_u, out_w);
}

// round 4
// speedup vs baseline: 2.0009x; 1.2115x over previous
#include <cuda_runtime.h>
#include <cstdint>

#define NSPB 32                    // sites per block
#define THREADS (NSPB * 9)         // 288
#define S_STRIDE 148               // floats per site in smem (144 + 4 pad)

__device__ __forceinline__ unsigned long long pack2(float lo, float hi) {
    unsigned long long r;
    asm("mov.b64 %0, {%1,%2};" : "=l"(r) : "f"(lo), "f"(hi));
    return r;
}
__device__ __forceinline__ void unpack2(unsigned long long v, float& lo, float& hi) {
    asm("mov.b64 {%0,%1}, %2;" : "=f"(lo), "=f"(hi) : "l"(v));
}
__device__ __forceinline__ unsigned long long ffma2(unsigned long long a, unsigned long long b,
                                                    unsigned long long c) {
    unsigned long long d;
    asm("fma.rn.f32x2 %0, %1, %2, %3;" : "=l"(d) : "l"(a), "l"(b), "l"(c));
    return d;
}
__device__ __forceinline__ unsigned long long fmul2(unsigned long long a, unsigned long long b) {
    unsigned long long d;
    asm("mul.rn.f32x2 %0, %1, %2;" : "=l"(d) : "l"(a), "l"(b));
    return d;
}

// acc{R,I}[0..3] += weight8(vw) * (cR,cR)/(cI,cI); weights read as 2 natural LDS.128
__device__ __forceinline__ void mix_step(const ulonglong2* __restrict__ wvw,
                                         unsigned long long cpk,
                                         unsigned long long* accR,
                                         unsigned long long* accI)
{
    float cR, cI;
    unpack2(cpk, cR, cI);
    unsigned long long cRR = pack2(cR, cR);
    unsigned long long cII = pack2(cI, cI);
    ulonglong2 lo = wvw[0];       // (w0,w1),(w2,w3)
    ulonglong2 hi = wvw[1];       // (w4,w5),(w6,w7)
    accR[0] = ffma2(lo.x, cRR, accR[0]);
    accI[0] = ffma2(lo.x, cII, accI[0]);
    accR[1] = ffma2(lo.y, cRR, accR[1]);
    accI[1] = ffma2(lo.y, cII, accI[1]);
    accR[2] = ffma2(hi.x, cRR, accR[2]);
    accI[2] = ffma2(hi.x, cII, accI[2]);
    accR[3] = ffma2(hi.y, cRR, accR[3]);
    accI[3] = ffma2(hi.y, cII, accI[3]);
}

__global__ __launch_bounds__(THREADS, 3)
void lbilin_kernel(const float* __restrict__ u,
                   const float* __restrict__ w1,
                   const float* __restrict__ w2,
                   const float* __restrict__ weight,
                   float* __restrict__ out_u,
                   float* __restrict__ out_w)
{
    __shared__ float s_w1[NSPB * S_STRIDE];
    __shared__ float s_w2[NSPB * S_STRIDE];
    __shared__ float s_wt[81 * 8];     // s_wt[vw*8 + u] = weight[u*81 + vw]

    const int tid = threadIdx.x;
    const long long site0 = (long long)blockIdx.x * NSPB;

    // ---- u passthrough: 32 sites * 72 floats = 576 float4 per block ----
    {
        const float4* src = (const float4*)(u + site0 * 72);
        float4*       dst = (float4*)(out_u + site0 * 72);
        #pragma unroll
        for (int idx = tid; idx < NSPB * 18; idx += THREADS)
            dst[idx] = src[idx];
    }

    // ---- weight transpose into smem: [vw][u] ----
    for (int d = tid; d < 648; d += THREADS) {
        int uo = d & 7;
        int vw = d >> 3;
        s_wt[d] = weight[uo * 81 + vw];
    }

    // ---- stage w1, w2 tiles (144 contiguous floats/site) ----
    {
        const float4* g1 = (const float4*)(w1 + site0 * 144);
        const float4* g2 = (const float4*)(w2 + site0 * 144);
        for (int idx = tid; idx < NSPB * 36; idx += THREADS) {
            int s = idx / 36;
            int q = idx - s * 36;
            ((float4*)(s_w1 + s * S_STRIDE))[q] = g1[idx];
            ((float4*)(s_w2 + s * S_STRIDE))[q] = g2[idx];
        }
    }
    __syncthreads();

    const int sl = tid / 9;
    const int ik = tid - sl * 9;
    const int i  = ik / 3;
    const int k  = ik - i * 3;
    const long long site = site0 + sl;

    const unsigned long long* w1p = (const unsigned long long*)(s_w1 + sl * S_STRIDE);
    const unsigned long long* w2p = (const unsigned long long*)(s_w2 + sl * S_STRIDE);
    const ulonglong2* wt2 = (const ulonglong2*)s_wt;   // 2 per vw

    unsigned long long accR[4], accI[4];
    #pragma unroll
    for (int h = 0; h < 4; h++) { accR[h] = 0ULL; accI[h] = 0ULL; }

    const unsigned long long NEGPOS = pack2(-1.0f, 1.0f);

    // ---- two passes over w-halves: keeps b cache at 12 u64 (24 regs) ----
    #pragma unroll
    for (int half = 0; half < 2; half++) {
        const int wbase = half * 4;

        unsigned long long b[12];
        #pragma unroll
        for (int w = 0; w < 4; w++)
            #pragma unroll
            for (int j = 0; j < 3; j++)
                b[w * 3 + j] = w2p[(wbase + w) * 9 + j * 3 + k];

        #pragma unroll 2
        for (int v = 0; v < 8; v++) {
            float a0R, a0I, a1R, a1I, a2R, a2I;
            unpack2(w1p[v * 9 + i * 3 + 0], a0R, a0I);
            unpack2(w1p[v * 9 + i * 3 + 1], a1R, a1I);
            unpack2(w1p[v * 9 + i * 3 + 2], a2R, a2I);
            unsigned long long aR0 = pack2(a0R, a0R), aR1 = pack2(a1R, a1R), aR2 = pack2(a2R, a2R);
            unsigned long long aI0 = pack2(a0I, a0I), aI1 = pack2(a1I, a1I), aI2 = pack2(a2I, a2I);

            #pragma unroll
            for (int w = 0; w < 4; w++) {
                // s = (Sum aR*bR, Sum aR*bI) ; t = (Sum aI*bR, Sum aI*bI)
                unsigned long long s2 = fmul2(aR0, b[w * 3 + 0]);
                s2 = ffma2(aR1, b[w * 3 + 1], s2);
                s2 = ffma2(aR2, b[w * 3 + 2], s2);
                unsigned long long t2 = fmul2(aI0, b[w * 3 + 0]);
                t2 = ffma2(aI1, b[w * 3 + 1], t2);
                t2 = ffma2(aI2, b[w * 3 + 2], t2);
                // cval = (s.lo - t.hi, s.hi + t.lo) = swap(t)*(-1,+1) + s
                float tl, th;
                unpack2(t2, tl, th);
                unsigned long long cpk = ffma2(pack2(th, tl), NEGPOS, s2);
                mix_step(wt2 + (v * 9 + wbase + w) * 2, cpk, accR, accI);
            }
        }
        // v = 8: A is identity -> c[8,w] = B_w[i,k]
        #pragma unroll
        for (int w = 0; w < 4; w++)
            mix_step(wt2 + (8 * 9 + wbase + w) * 2, w2p[(wbase + w) * 9 + i * 3 + k],
                     accR, accI);
    }

    // w = 8 column: B identity -> c[v,8] = A_v[i,k]
    #pragma unroll
    for (int v = 0; v < 8; v++)
        mix_step(wt2 + (v * 9 + 8) * 2, w1p[v * 9 + i * 3 + k], accR, accI);
    // (v,w) = (8,8): c = identity[i,k]  (compile-free constant)
    mix_step(wt2 + (8 * 9 + 8) * 2, pack2((i == k) ? 1.0f : 0.0f, 0.0f), accR, accI);

    // store w[u, i, k, {re,im}] : float2 at offset (u*9 + ik)*2
    float2* op = (float2*)(out_w + site * 144 + ik * 2);
    #pragma unroll
    for (int h = 0; h < 4; h++) {
        float r0, r1, i0, i1;
        unpack2(accR[h], r0, r1);
        unpack2(accI[h], i0, i1);
        op[(2 * h + 0) * 9] = make_float2(r0, i0);
        op[(2 * h + 1) * 9] = make_float2(r1, i1);
    }
}

extern "C" void kernel_launch(void* const* d_in, const int* in_sizes, int n_in,
                              void* d_out, int out_size) {
    const float* u  = (const float*)d_in[0];
    const float* w1 = (const float*)d_in[1];
    const float* w2 = (const float*)d_in[2];
    const float* wt = (const float*)d_in[3];

    int nsites = in_sizes[1] / 144;          // 65536
    float* out   = (float*)d_out;
    float* out_u = out;                       // u passthrough first
    float* out_w = out + (long long)nsites * 72;  // then mixed output

    int blocks = nsites / NSPB;               // 2048
    lbilin_kernel<<<blocks, THREADS>>>(u, w1, w2, wt, out_u, out_w);
}